// round 10
// baseline (speedup 1.0000x reference)
#include <cuda_runtime.h>

// SparseEmbedding: out[b, :] = sum_n vals[b,n] * kernel[idx[b,n], :] + bias
// BATCH=4096, NNZ=32, VOCAB=1e6, DIM=64. float32 everywhere, idx int32.
//
// R9: single-wave variant. R8 (8.32us) had grid=512 CTAs with 444 resident
// -> 68-CTA second wave pays an unoverlapped gather round trip. Here each
// warp handles TWO rows with both register gather batches live (64 loads
// in flight per warp, ~55 effective = per-warp LDG cap), grid=256 CTAs =
// one resident wave, no tail. __ldcg gathers (L2-direct), bias folded.

#define BATCH 4096
#define NNZ   32
#define DIM   64

__global__ void __launch_bounds__(256, 1) sparse_embedding_kernel(
    const int*   __restrict__ idx,
    const float* __restrict__ vals,
    const float* __restrict__ table,
    const float* __restrict__ bias,
    float*       __restrict__ out)
{
    const int gwarp = (blockIdx.x * blockDim.x + threadIdx.x) >> 5;
    const int lane  = threadIdx.x & 31;

    const int r0 = gwarp * 2;        // first batch row
    const int r1 = gwarp * 2 + 1;    // second batch row

    // Each lane holds one (idx, val) pair per row; broadcast via shfl.
    const int   idx0 = __ldg(idx  + r0 * NNZ + lane);
    const int   idx1 = __ldg(idx  + r1 * NNZ + lane);
    const float val0 = __ldg(vals + r0 * NNZ + lane);
    const float val1 = __ldg(vals + r1 * NNZ + lane);

    // Phase 1: issue ALL 64 gather loads (both rows) before any consumer.
    float2 kv0[NNZ], kv1[NNZ];
#pragma unroll
    for (int n = 0; n < NNZ; ++n) {
        const int id = __shfl_sync(0xffffffffu, idx0, n);
        kv0[n] = __ldcg(reinterpret_cast<const float2*>(
            table + (size_t)id * DIM) + lane);
    }
#pragma unroll
    for (int n = 0; n < NNZ; ++n) {
        const int id = __shfl_sync(0xffffffffu, idx1, n);
        kv1[n] = __ldcg(reinterpret_cast<const float2*>(
            table + (size_t)id * DIM) + lane);
    }

    // Phase 2: accumulate row 0 (its loads complete first), then row 1.
    const float2 b = __ldg(reinterpret_cast<const float2*>(bias) + lane);

    float2 acc0 = b;
#pragma unroll
    for (int n = 0; n < NNZ; ++n) {
        const float v = __shfl_sync(0xffffffffu, val0, n);
        acc0.x = fmaf(v, kv0[n].x, acc0.x);
        acc0.y = fmaf(v, kv0[n].y, acc0.y);
    }
    reinterpret_cast<float2*>(out + (size_t)r0 * DIM)[lane] = acc0;

    float2 acc1 = b;
#pragma unroll
    for (int n = 0; n < NNZ; ++n) {
        const float v = __shfl_sync(0xffffffffu, val1, n);
        acc1.x = fmaf(v, kv1[n].x, acc1.x);
        acc1.y = fmaf(v, kv1[n].y, acc1.y);
    }
    reinterpret_cast<float2*>(out + (size_t)r1 * DIM)[lane] = acc1;
}

extern "C" void kernel_launch(void* const* d_in, const int* in_sizes, int n_in,
                              void* d_out, int out_size)
{
    const int*   idx   = (const int*)  d_in[0];
    const float* vals  = (const float*)d_in[1];
    const float* table = (const float*)d_in[2];
    const float* bias  = (const float*)d_in[3];
    float*       out   = (float*)d_out;

    // 2048 warps (2 rows each), 8 warps per 256-thread CTA -> 256 CTAs.
    // 256 CTAs fit in ONE resident wave (<=2 CTAs/SM needed) -> no tail.
    const int threads = 256;
    const int blocks  = (BATCH / 2 * 32) / threads;
    sparse_embedding_kernel<<<blocks, threads>>>(idx, vals, table, bias, out);
}

// round 11
// speedup vs baseline: 1.0221x; 1.0221x over previous
#include <cuda_runtime.h>

// SparseEmbedding: out[b, :] = sum_n vals[b,n] * kernel[idx[b,n], :] + bias
// BATCH=4096, NNZ=32, VOCAB=1e6, DIM=64. float32 everywhere, idx int32.
//
// R10: single-wave + pipelined gather. R8 (8.32us, regs=80) left a 68-CTA
// straggler wave (3 CTAs/SM x 148 = 444 < 512). Capping regs at 64 via
// __launch_bounds__(256, 4) gives 4 CTAs/SM -> 592 slots -> ONE wave.
// To fit the budget, the 32-row gather is pipelined as two 16-row register
// batches (load b0 -> accumulate b0 -> load b1 -> accumulate b1), reusing
// the same 32 kv registers. Per-SM in-flight = ~28 warps x 16 loads = ~448,
// still above the per-SM queue knee, so bandwidth supply stays saturated.

#define BATCH 4096
#define NNZ   32
#define DIM   64
#define HALF  16

__global__ void __launch_bounds__(256, 4) sparse_embedding_kernel(
    const int*   __restrict__ idx,
    const float* __restrict__ vals,
    const float* __restrict__ table,
    const float* __restrict__ bias,
    float*       __restrict__ out)
{
    const int gwarp = (blockIdx.x * blockDim.x + threadIdx.x) >> 5;
    const int lane  = threadIdx.x & 31;

    // Each lane holds one (idx, val) pair for this row; broadcast via shfl.
    const int   my_idx = __ldg(idx  + gwarp * NNZ + lane);
    const float my_val = __ldg(vals + gwarp * NNZ + lane);

    float2 acc = __ldg(reinterpret_cast<const float2*>(bias) + lane);
    float2 kv[HALF];

    // Batch 0: issue 16 independent gathers, then accumulate.
#pragma unroll
    for (int n = 0; n < HALF; ++n) {
        const int id = __shfl_sync(0xffffffffu, my_idx, n);
        kv[n] = __ldcg(reinterpret_cast<const float2*>(
            table + (size_t)id * DIM) + lane);
    }
#pragma unroll
    for (int n = 0; n < HALF; ++n) {
        const float v = __shfl_sync(0xffffffffu, my_val, n);
        acc.x = fmaf(v, kv[n].x, acc.x);
        acc.y = fmaf(v, kv[n].y, acc.y);
    }

    // Batch 1: reuse the same kv registers.
#pragma unroll
    for (int n = 0; n < HALF; ++n) {
        const int id = __shfl_sync(0xffffffffu, my_idx, HALF + n);
        kv[n] = __ldcg(reinterpret_cast<const float2*>(
            table + (size_t)id * DIM) + lane);
    }
#pragma unroll
    for (int n = 0; n < HALF; ++n) {
        const float v = __shfl_sync(0xffffffffu, my_val, HALF + n);
        acc.x = fmaf(v, kv[n].x, acc.x);
        acc.y = fmaf(v, kv[n].y, acc.y);
    }

    reinterpret_cast<float2*>(out + (size_t)gwarp * DIM)[lane] = acc;
}

extern "C" void kernel_launch(void* const* d_in, const int* in_sizes, int n_in,
                              void* d_out, int out_size)
{
    const int*   idx   = (const int*)  d_in[0];
    const float* vals  = (const float*)d_in[1];
    const float* table = (const float*)d_in[2];
    const float* bias  = (const float*)d_in[3];
    float*       out   = (float*)d_out;

    // 4096 warps, 8 warps per 256-thread CTA -> 512 CTAs; with <=64 regs
    // that's 4 CTAs/SM x 148 = 592 slots -> a single resident wave.
    const int threads = 256;
    const int blocks  = (BATCH * 32) / threads;
    sparse_embedding_kernel<<<blocks, threads>>>(idx, vals, table, bias, out);
}